// round 8
// baseline (speedup 1.0000x reference)
#include <cuda_runtime.h>
#include <cstdint>

#define NUM_CLASSES    32000
#define ROW_BYTES      128000
#define ALPHA          0.95f

#define THREADS        512
#define NCONS          480            // 15 consumer warps
#define PROD_WARP      15

#define CHUNKS_PER_ROW 4
#define CHUNK_BYTES    32000
#define CHUNK_F4       2000
#define CHUNK_FLOATS   8000
#define NSLOTS         7              // 7 * 32000 = 224000 B ring
#define LAG            2              // store-commit -> slot-reload slack

// smem layout (dynamic):
//   [0,56)     full mbarriers   (7 x 8B)
//   [64,120)   scaled mbarriers (7 x 8B)
//   [128,188)  swarp[15]
//   [192,196)  sS
//   [512, 512+224000) ring slots
#define OFF_FULL    0
#define OFF_SCALED  64
#define OFF_SWARP   128
#define OFF_SS      192
#define OFF_SLOTS   512
#define SMEM_TOTAL  (OFF_SLOTS + NSLOTS * CHUNK_BYTES)   // 224512

__device__ __forceinline__ uint32_t smem_u32(const void* p) {
    uint32_t a;
    asm("{ .reg .u64 t; cvta.to.shared.u64 t, %1; cvt.u32.u64 %0, t; }"
        : "=r"(a) : "l"(p));
    return a;
}
__device__ __forceinline__ void mbar_init(uint32_t addr, uint32_t cnt) {
    asm volatile("mbarrier.init.shared.b64 [%0], %1;" :: "r"(addr), "r"(cnt) : "memory");
}
__device__ __forceinline__ void mbar_expect_tx(uint32_t addr, uint32_t bytes) {
    asm volatile("mbarrier.arrive.expect_tx.shared.b64 _, [%0], %1;"
                 :: "r"(addr), "r"(bytes) : "memory");
}
__device__ __forceinline__ void mbar_arrive(uint32_t addr) {
    asm volatile("mbarrier.arrive.shared.b64 _, [%0];" :: "r"(addr) : "memory");
}
__device__ __forceinline__ void mbar_wait(uint32_t addr, uint32_t parity) {
    uint32_t done;
    asm volatile(
        "{\n\t.reg .pred p;\n\t"
        "mbarrier.try_wait.parity.acquire.cta.shared::cta.b64 p, [%1], %2;\n\t"
        "selp.b32 %0, 1, 0, p;\n\t}"
        : "=r"(done) : "r"(addr), "r"(parity) : "memory");
    if (!done) {
        asm volatile(
            "{\n\t.reg .pred P1;\n\t"
            "W_%=:\n\t"
            "mbarrier.try_wait.parity.acquire.cta.shared::cta.b64 P1, [%0], %1, 0x989680;\n\t"
            "@P1 bra.uni D_%=;\n\t"
            "bra.uni W_%=;\n\t"
            "D_%=:\n\t}"
            :: "r"(addr), "r"(parity) : "memory");
    }
}
__device__ __forceinline__ void bulk_g2s(uint32_t dst, const void* src,
                                         uint32_t bytes, uint32_t mbar) {
    asm volatile(
        "cp.async.bulk.shared::cluster.global.mbarrier::complete_tx::bytes "
        "[%0], [%1], %2, [%3];"
        :: "r"(dst), "l"(src), "r"(bytes), "r"(mbar) : "memory");
}
__device__ __forceinline__ void bulk_s2g(void* dst, uint32_t src, uint32_t bytes) {
    asm volatile(
        "cp.async.bulk.global.shared::cta.bulk_group [%0], [%1], %2;"
        :: "l"(dst), "r"(src), "r"(bytes) : "memory");
}
__device__ __forceinline__ void bulk_commit() {
    asm volatile("cp.async.bulk.commit_group;" ::: "memory");
}
template <int N>
__device__ __forceinline__ void bulk_wait_read() {
    asm volatile("cp.async.bulk.wait_group.read %0;" :: "n"(N) : "memory");
}
__device__ __forceinline__ void bulk_wait_all() {
    asm volatile("cp.async.bulk.wait_group 0;" ::: "memory");
}
__device__ __forceinline__ void fence_async_shared() {
    asm volatile("fence.proxy.async.shared::cta;" ::: "memory");
}

extern __shared__ char smem[];

__global__ __launch_bounds__(THREADS, 1)
void smooth_kernel(const float* __restrict__ in,
                   const int* __restrict__ labels,
                   float* __restrict__ out,
                   int batch)
{
    const uint32_t sbase   = smem_u32(smem);
    const uint32_t full0   = sbase + OFF_FULL;
    const uint32_t scaled0 = sbase + OFF_SCALED;
    float* swarp = reinterpret_cast<float*>(smem + OFF_SWARP);
    float* sSp   = reinterpret_cast<float*>(smem + OFF_SS);
    char*  slots = smem + OFF_SLOTS;
    const uint32_t slots_u = sbase + OFF_SLOTS;

    const int tid = threadIdx.x;
    const int wid = tid >> 5;
    const int lid = tid & 31;

    if (tid == 0) {
        #pragma unroll
        for (int s = 0; s < NSLOTS; s++) {
            mbar_init(full0   + 8u * s, 1);    // TMA expect_tx completion
            mbar_init(scaled0 + 8u * s, 15);   // one arrive per consumer warp
        }
    }
    __syncthreads();

    // chunks handled by this CTA
    const int nrows = (batch - blockIdx.x + gridDim.x - 1) / gridDim.x;
    const int T = nrows * CHUNKS_PER_ROW;

    if (wid == PROD_WARP) {
        // ---- fused producer (R6 structure): pipelined store + lagged load ----
        // iter g: store stage flushes slot g%NSLOTS (occupant chunk g-NSLOTS);
        //         load stage loads chunk g-LAG into slot (g-LAG)%NSLOTS,
        //         guarded by wait_group.read<LAG> (that slot's store committed
        //         LAG iterations earlier, so its smem read has drained).
        if (lid == 0) {
            float* dsts[NSLOTS];
            int s_slot = 0, sphase = 1;        // flipped: first NSLOTS waits pass

            const int GMAX = T + NSLOTS;       // NSLOTS > LAG
            for (int g = 0; g < GMAX; g++) {
                // ---- store stage ----
                mbar_wait(scaled0 + 8u * s_slot, (uint32_t)sphase);
                if (g >= NSLOTS) {
                    fence_async_shared();
                    bulk_s2g(dsts[s_slot],
                             slots_u + (uint32_t)s_slot * CHUNK_BYTES,
                             CHUNK_BYTES);
                    bulk_commit();
                }
                if (++s_slot == NSLOTS) { s_slot = 0; sphase ^= 1; }

                // ---- load stage (lags by LAG) ----
                const int cl = g - LAG;
                if (cl >= 0 && cl < T) {
                    const int l_slot = cl % NSLOTS;
                    bulk_wait_read<LAG>();
                    const int rl  = cl >> 2;          // local row
                    const int cc  = cl & 3;           // chunk in row
                    const int r   = blockIdx.x + rl * gridDim.x;
                    const char* src = reinterpret_cast<const char*>(in)
                                    + (size_t)r * ROW_BYTES
                                    + (size_t)cc * CHUNK_BYTES;
                    dsts[l_slot] = out + (size_t)r * NUM_CLASSES
                                       + (size_t)cc * CHUNK_FLOATS;
                    mbar_expect_tx(full0 + 8u * l_slot, CHUNK_BYTES);
                    bulk_g2s(slots_u + (uint32_t)l_slot * CHUNK_BYTES,
                             src, CHUNK_BYTES,
                             full0 + 8u * l_slot);
                }
            }
            bulk_wait_all();   // all output stores complete before exit
        }
    } else {
        // ---------- consumers (15 warps): sum, reduce, scale in place ----------
        int slot = 0, cphase = 0;
        for (int r = blockIdx.x; r < batch; r += gridDim.x) {
            const int label = __ldg(labels + r);
            const int lvec  = label >> 2;
            const int lcomp = label & 3;
            const int c_l   = lvec / CHUNK_F4;
            const int loff  = lvec % CHUNK_F4;

            const int row_slot0 = slot;

            // -- sum phase --
            float local = 0.0f;
            for (int c = 0; c < CHUNKS_PER_ROW; c++) {
                mbar_wait(full0 + 8u * slot, (uint32_t)cphase);
                const float4* ch =
                    reinterpret_cast<const float4*>(slots + (size_t)slot * CHUNK_BYTES);
                for (int i = tid; i < CHUNK_F4; i += NCONS) {
                    float4 v = ch[i];
                    local += (v.x + v.y) + (v.z + v.w);
                }
                if (++slot == NSLOTS) { slot = 0; cphase ^= 1; }
            }

            // label element: all row chunks resident until this row's slots freed
            int lslot = row_slot0 + c_l; if (lslot >= NSLOTS) lslot -= NSLOTS;
            const float t = *reinterpret_cast<const float*>(
                slots + (size_t)lslot * CHUNK_BYTES
                      + ((size_t)loff * 16 + (size_t)lcomp * 4));

            // -- reduce S across 15 warps --
            #pragma unroll
            for (int o = 16; o > 0; o >>= 1)
                local += __shfl_down_sync(0xffffffffu, local, o);
            if (lid == 0) swarp[wid] = local;
            asm volatile("bar.sync 1, %0;" :: "n"(NCONS) : "memory");
            if (wid == 0) {
                float v = (lid < 15) ? swarp[lid] : 0.0f;
                #pragma unroll
                for (int o = 8; o > 0; o >>= 1)
                    v += __shfl_down_sync(0xffffffffu, v, o);
                if (lid == 0) *sSp = v;
            }
            asm volatile("bar.sync 1, %0;" :: "n"(NCONS) : "memory");

            const float S    = *sSp;
            const float s    = ALPHA / (1.0f + S - 2.0f * t);
            const float corr = 1.0f - s * S;

            // -- scale phase: in-place smem, hand slots to producer --
            int sslot = row_slot0;
            for (int c = 0; c < CHUNKS_PER_ROW; c++) {
                float4* ch =
                    reinterpret_cast<float4*>(slots + (size_t)sslot * CHUNK_BYTES);
                const bool lchunk = (c == c_l);
                for (int i = tid; i < CHUNK_F4; i += NCONS) {
                    float4 v = ch[i];
                    float4 o = make_float4(s * v.x, s * v.y, s * v.z, s * v.w);
                    if (lchunk && i == loff) {
                        o.x += (lcomp == 0) ? corr : 0.0f;
                        o.y += (lcomp == 1) ? corr : 0.0f;
                        o.z += (lcomp == 2) ? corr : 0.0f;
                        o.w += (lcomp == 3) ? corr : 0.0f;
                    }
                    ch[i] = o;
                }
                __syncwarp();
                if (lid == 0) mbar_arrive(scaled0 + 8u * sslot);
                if (++sslot == NSLOTS) sslot = 0;
            }
        }
    }
}

extern "C" void kernel_launch(void* const* d_in, const int* in_sizes, int n_in,
                              void* d_out, int out_size)
{
    const float* logits = (const float*)d_in[0];
    const int*   labels = (const int*)d_in[1];
    float*       out    = (float*)d_out;

    const int batch = in_sizes[1];

    cudaFuncSetAttribute(smooth_kernel,
                         cudaFuncAttributeMaxDynamicSharedMemorySize, SMEM_TOTAL);

    int dev = 0, sms = 148;
    cudaGetDevice(&dev);
    cudaDeviceGetAttribute(&sms, cudaDevAttrMultiProcessorCount, dev);
    int grid = sms < batch ? sms : batch;

    smooth_kernel<<<grid, THREADS, SMEM_TOTAL>>>(logits, labels, out, batch);
}

// round 9
// speedup vs baseline: 1.0360x; 1.0360x over previous
#include <cuda_runtime.h>
#include <cstdint>

#define NUM_CLASSES    32000
#define ROW_BYTES      128000
#define ALPHA          0.95f

#define THREADS        352            // 10 consumer warps + 1 producer warp
#define NCONS          320
#define NCW            10             // consumer warps
#define PROD_WARP      10

#define CHUNKS_PER_ROW 5
#define CHUNK_BYTES    25600          // 1600 float4; 1600 = 5 * 320 exactly
#define CHUNK_F4       1600
#define CHUNK_FLOATS   6400
#define F4_PER_THREAD  5              // per chunk
#define NSLOTS         7              // 7 * 25600 = 179200 B ring (>= full row)
#define LAG            2              // store-commit -> slot-reload slack

// smem layout (dynamic):
//   [0,56)     full mbarriers   (7 x 8B)
//   [64,120)   scaled mbarriers (7 x 8B)
//   [128,168)  swarp[10]
//   [192,196)  sS
//   [196,200)  sT
//   [512, 512+179200) ring slots
#define OFF_FULL    0
#define OFF_SCALED  64
#define OFF_SWARP   128
#define OFF_SS      192
#define OFF_ST      196
#define OFF_SLOTS   512
#define SMEM_TOTAL  (OFF_SLOTS + NSLOTS * CHUNK_BYTES)   // 179712

__device__ __forceinline__ uint32_t smem_u32(const void* p) {
    uint32_t a;
    asm("{ .reg .u64 t; cvta.to.shared.u64 t, %1; cvt.u32.u64 %0, t; }"
        : "=r"(a) : "l"(p));
    return a;
}
__device__ __forceinline__ void mbar_init(uint32_t addr, uint32_t cnt) {
    asm volatile("mbarrier.init.shared.b64 [%0], %1;" :: "r"(addr), "r"(cnt) : "memory");
}
__device__ __forceinline__ void mbar_expect_tx(uint32_t addr, uint32_t bytes) {
    asm volatile("mbarrier.arrive.expect_tx.shared.b64 _, [%0], %1;"
                 :: "r"(addr), "r"(bytes) : "memory");
}
__device__ __forceinline__ void mbar_arrive(uint32_t addr) {
    asm volatile("mbarrier.arrive.shared.b64 _, [%0];" :: "r"(addr) : "memory");
}
__device__ __forceinline__ void mbar_wait(uint32_t addr, uint32_t parity) {
    uint32_t done;
    asm volatile(
        "{\n\t.reg .pred p;\n\t"
        "mbarrier.try_wait.parity.acquire.cta.shared::cta.b64 p, [%1], %2;\n\t"
        "selp.b32 %0, 1, 0, p;\n\t}"
        : "=r"(done) : "r"(addr), "r"(parity) : "memory");
    if (!done) {
        asm volatile(
            "{\n\t.reg .pred P1;\n\t"
            "W_%=:\n\t"
            "mbarrier.try_wait.parity.acquire.cta.shared::cta.b64 P1, [%0], %1, 0x989680;\n\t"
            "@P1 bra.uni D_%=;\n\t"
            "bra.uni W_%=;\n\t"
            "D_%=:\n\t}"
            :: "r"(addr), "r"(parity) : "memory");
    }
}
__device__ __forceinline__ void bulk_g2s(uint32_t dst, const void* src,
                                         uint32_t bytes, uint32_t mbar) {
    asm volatile(
        "cp.async.bulk.shared::cluster.global.mbarrier::complete_tx::bytes "
        "[%0], [%1], %2, [%3];"
        :: "r"(dst), "l"(src), "r"(bytes), "r"(mbar) : "memory");
}
__device__ __forceinline__ void bulk_s2g(void* dst, uint32_t src, uint32_t bytes) {
    asm volatile(
        "cp.async.bulk.global.shared::cta.bulk_group [%0], [%1], %2;"
        :: "l"(dst), "r"(src), "r"(bytes) : "memory");
}
__device__ __forceinline__ void bulk_commit() {
    asm volatile("cp.async.bulk.commit_group;" ::: "memory");
}
template <int N>
__device__ __forceinline__ void bulk_wait_read() {
    asm volatile("cp.async.bulk.wait_group.read %0;" :: "n"(N) : "memory");
}
__device__ __forceinline__ void bulk_wait_all() {
    asm volatile("cp.async.bulk.wait_group 0;" ::: "memory");
}
__device__ __forceinline__ void fence_async_shared() {
    asm volatile("fence.proxy.async.shared::cta;" ::: "memory");
}

extern __shared__ char smem[];

__global__ __launch_bounds__(THREADS, 1)
void smooth_kernel(const float* __restrict__ in,
                   const int* __restrict__ labels,
                   float* __restrict__ out,
                   int batch)
{
    const uint32_t sbase   = smem_u32(smem);
    const uint32_t full0   = sbase + OFF_FULL;
    const uint32_t scaled0 = sbase + OFF_SCALED;
    float* swarp = reinterpret_cast<float*>(smem + OFF_SWARP);
    float* sSp   = reinterpret_cast<float*>(smem + OFF_SS);
    float* sTp   = reinterpret_cast<float*>(smem + OFF_ST);
    char*  slots = smem + OFF_SLOTS;
    const uint32_t slots_u = sbase + OFF_SLOTS;

    const int tid = threadIdx.x;
    const int wid = tid >> 5;
    const int lid = tid & 31;

    if (tid == 0) {
        #pragma unroll
        for (int s = 0; s < NSLOTS; s++) {
            mbar_init(full0   + 8u * s, 1);     // TMA expect_tx completion
            mbar_init(scaled0 + 8u * s, NCW);   // one arrive per consumer warp
        }
    }
    __syncthreads();

    // chunks handled by this CTA
    const int nrows = (batch - blockIdx.x + gridDim.x - 1) / gridDim.x;
    const int T = nrows * CHUNKS_PER_ROW;

    if (wid == PROD_WARP) {
        // ---- fused producer: pipelined store + lagged load (R6 structure) ----
        if (lid == 0) {
            float* dsts[NSLOTS];
            int s_slot = 0, sphase = 1;        // flipped: first NSLOTS waits pass

            const int GMAX = T + NSLOTS;       // NSLOTS > LAG
            for (int g = 0; g < GMAX; g++) {
                // ---- store stage: flush occupant of slot g%NSLOTS ----
                mbar_wait(scaled0 + 8u * s_slot, (uint32_t)sphase);
                if (g >= NSLOTS) {
                    fence_async_shared();
                    bulk_s2g(dsts[s_slot],
                             slots_u + (uint32_t)s_slot * CHUNK_BYTES,
                             CHUNK_BYTES);
                    bulk_commit();
                }
                if (++s_slot == NSLOTS) { s_slot = 0; sphase ^= 1; }

                // ---- load stage (lags by LAG iterations) ----
                const int cl = g - LAG;
                if (cl >= 0 && cl < T) {
                    const int l_slot = cl % NSLOTS;
                    bulk_wait_read<LAG>();     // that slot's store read drained
                    const int rl  = cl / CHUNKS_PER_ROW;
                    const int cc  = cl - rl * CHUNKS_PER_ROW;
                    const int r   = blockIdx.x + rl * gridDim.x;
                    const char* src = reinterpret_cast<const char*>(in)
                                    + (size_t)r * ROW_BYTES
                                    + (size_t)cc * CHUNK_BYTES;
                    dsts[l_slot] = out + (size_t)r * NUM_CLASSES
                                       + (size_t)cc * CHUNK_FLOATS;
                    mbar_expect_tx(full0 + 8u * l_slot, CHUNK_BYTES);
                    bulk_g2s(slots_u + (uint32_t)l_slot * CHUNK_BYTES,
                             src, CHUNK_BYTES,
                             full0 + 8u * l_slot);
                }
            }
            bulk_wait_all();   // all output stores complete before exit
        }
    } else {
        // ------- consumers (10 warps / 320 threads): sum, reduce, scale -------
        int slot = 0, cphase = 0;
        for (int r = blockIdx.x; r < batch; r += gridDim.x) {
            const int label = __ldg(labels + r);
            const int lvec  = label >> 2;
            const int lcomp = label & 3;
            const int c_l   = lvec / CHUNK_F4;    // chunk holding label elem
            const int loff  = lvec % CHUNK_F4;    // f4 index inside chunk

            const int row_slot0 = slot;

            // -- sum phase: exact partition, no bounds checks --
            float local = 0.0f;
            for (int c = 0; c < CHUNKS_PER_ROW; c++) {
                mbar_wait(full0 + 8u * slot, (uint32_t)cphase);
                const float4* ch =
                    reinterpret_cast<const float4*>(slots + (size_t)slot * CHUNK_BYTES);
                #pragma unroll
                for (int k = 0; k < F4_PER_THREAD; k++) {
                    float4 v = ch[tid + k * NCONS];
                    local += (v.x + v.y) + (v.z + v.w);
                }
                // grab label element while this chunk is guaranteed resident
                if (c == c_l && tid == 0) {
                    *sTp = *reinterpret_cast<const float*>(
                        slots + (size_t)slot * CHUNK_BYTES
                              + ((size_t)loff * 16 + (size_t)lcomp * 4));
                }
                if (++slot == NSLOTS) { slot = 0; cphase ^= 1; }
            }

            // -- reduce S across 10 warps --
            #pragma unroll
            for (int o = 16; o > 0; o >>= 1)
                local += __shfl_down_sync(0xffffffffu, local, o);
            if (lid == 0) swarp[wid] = local;
            asm volatile("bar.sync 1, %0;" :: "n"(NCONS) : "memory");
            if (wid == 0) {
                float v = (lid < NCW) ? swarp[lid] : 0.0f;
                #pragma unroll
                for (int o = 8; o > 0; o >>= 1)
                    v += __shfl_down_sync(0xffffffffu, v, o);
                if (lid == 0) *sSp = v;
            }
            asm volatile("bar.sync 1, %0;" :: "n"(NCONS) : "memory");

            const float S    = *sSp;
            const float t    = *sTp;
            const float s    = ALPHA / (1.0f + S - 2.0f * t);
            const float corr = 1.0f - s * S;

            // -- scale phase: in-place smem, hand slots to producer --
            int sslot = row_slot0;
            for (int c = 0; c < CHUNKS_PER_ROW; c++) {
                float4* ch =
                    reinterpret_cast<float4*>(slots + (size_t)sslot * CHUNK_BYTES);
                const bool lchunk = (c == c_l);
                #pragma unroll
                for (int k = 0; k < F4_PER_THREAD; k++) {
                    const int i = tid + k * NCONS;
                    float4 v = ch[i];
                    float4 o = make_float4(s * v.x, s * v.y, s * v.z, s * v.w);
                    if (lchunk && i == loff) {
                        o.x += (lcomp == 0) ? corr : 0.0f;
                        o.y += (lcomp == 1) ? corr : 0.0f;
                        o.z += (lcomp == 2) ? corr : 0.0f;
                        o.w += (lcomp == 3) ? corr : 0.0f;
                    }
                    ch[i] = o;
                }
                __syncwarp();
                if (lid == 0) mbar_arrive(scaled0 + 8u * sslot);
                if (++sslot == NSLOTS) sslot = 0;
            }
        }
    }
}

extern "C" void kernel_launch(void* const* d_in, const int* in_sizes, int n_in,
                              void* d_out, int out_size)
{
    const float* logits = (const float*)d_in[0];
    const int*   labels = (const int*)d_in[1];
    float*       out    = (float*)d_out;

    const int batch = in_sizes[1];

    cudaFuncSetAttribute(smooth_kernel,
                         cudaFuncAttributeMaxDynamicSharedMemorySize, SMEM_TOTAL);

    int dev = 0, sms = 148;
    cudaGetDevice(&dev);
    cudaDeviceGetAttribute(&sms, cudaDevAttrMultiProcessorCount, dev);
    int grid = sms < batch ? sms : batch;

    smooth_kernel<<<grid, THREADS, SMEM_TOTAL>>>(logits, labels, out, batch);
}

// round 10
// speedup vs baseline: 1.0425x; 1.0063x over previous
#include <cuda_runtime.h>
#include <cstdint>

#define NUM_CLASSES    32000
#define ROW_BYTES      128000
#define ALPHA          0.95f

#define THREADS        352            // 10 consumer warps + 1 producer warp
#define NCONS          320
#define NCW            10             // consumer warps
#define PROD_WARP      10

#define CHUNKS_PER_ROW 5
#define CHUNK_BYTES    25600          // 1600 float4; 1600 = 5 * 320 exactly
#define CHUNK_F4       1600
#define CHUNK_FLOATS   6400
#define F4_PER_THREAD  5              // per chunk
#define NSLOTS         8              // 8 * 25600 = 204800 B ring (row + 3 spare)
#define LAG            3              // store-commit -> slot-reload slack

// smem layout (dynamic):
//   [0,64)     full mbarriers   (8 x 8B)
//   [64,128)   scaled mbarriers (8 x 8B)
//   [128,168)  swarp[10]
//   [192,196)  sS
//   [196,200)  sT
//   [512, 512+204800) ring slots
#define OFF_FULL    0
#define OFF_SCALED  64
#define OFF_SWARP   128
#define OFF_SS      192
#define OFF_ST      196
#define OFF_SLOTS   512
#define SMEM_TOTAL  (OFF_SLOTS + NSLOTS * CHUNK_BYTES)   // 205312

__device__ __forceinline__ uint32_t smem_u32(const void* p) {
    uint32_t a;
    asm("{ .reg .u64 t; cvta.to.shared.u64 t, %1; cvt.u32.u64 %0, t; }"
        : "=r"(a) : "l"(p));
    return a;
}
__device__ __forceinline__ void mbar_init(uint32_t addr, uint32_t cnt) {
    asm volatile("mbarrier.init.shared.b64 [%0], %1;" :: "r"(addr), "r"(cnt) : "memory");
}
__device__ __forceinline__ void mbar_expect_tx(uint32_t addr, uint32_t bytes) {
    asm volatile("mbarrier.arrive.expect_tx.shared.b64 _, [%0], %1;"
                 :: "r"(addr), "r"(bytes) : "memory");
}
__device__ __forceinline__ void mbar_arrive(uint32_t addr) {
    asm volatile("mbarrier.arrive.shared.b64 _, [%0];" :: "r"(addr) : "memory");
}
__device__ __forceinline__ void mbar_wait(uint32_t addr, uint32_t parity) {
    uint32_t done;
    asm volatile(
        "{\n\t.reg .pred p;\n\t"
        "mbarrier.try_wait.parity.acquire.cta.shared::cta.b64 p, [%1], %2;\n\t"
        "selp.b32 %0, 1, 0, p;\n\t}"
        : "=r"(done) : "r"(addr), "r"(parity) : "memory");
    if (!done) {
        asm volatile(
            "{\n\t.reg .pred P1;\n\t"
            "W_%=:\n\t"
            "mbarrier.try_wait.parity.acquire.cta.shared::cta.b64 P1, [%0], %1, 0x989680;\n\t"
            "@P1 bra.uni D_%=;\n\t"
            "bra.uni W_%=;\n\t"
            "D_%=:\n\t}"
            :: "r"(addr), "r"(parity) : "memory");
    }
}
__device__ __forceinline__ void bulk_g2s(uint32_t dst, const void* src,
                                         uint32_t bytes, uint32_t mbar) {
    asm volatile(
        "cp.async.bulk.shared::cluster.global.mbarrier::complete_tx::bytes "
        "[%0], [%1], %2, [%3];"
        :: "r"(dst), "l"(src), "r"(bytes), "r"(mbar) : "memory");
}
__device__ __forceinline__ void bulk_s2g(void* dst, uint32_t src, uint32_t bytes) {
    asm volatile(
        "cp.async.bulk.global.shared::cta.bulk_group [%0], [%1], %2;"
        :: "l"(dst), "r"(src), "r"(bytes) : "memory");
}
__device__ __forceinline__ void bulk_commit() {
    asm volatile("cp.async.bulk.commit_group;" ::: "memory");
}
template <int N>
__device__ __forceinline__ void bulk_wait_read() {
    asm volatile("cp.async.bulk.wait_group.read %0;" :: "n"(N) : "memory");
}
__device__ __forceinline__ void bulk_wait_all() {
    asm volatile("cp.async.bulk.wait_group 0;" ::: "memory");
}
__device__ __forceinline__ void fence_async_shared() {
    asm volatile("fence.proxy.async.shared::cta;" ::: "memory");
}

extern __shared__ char smem[];

__global__ __launch_bounds__(THREADS, 1)
void smooth_kernel(const float* __restrict__ in,
                   const int* __restrict__ labels,
                   float* __restrict__ out,
                   int batch)
{
    const uint32_t sbase   = smem_u32(smem);
    const uint32_t full0   = sbase + OFF_FULL;
    const uint32_t scaled0 = sbase + OFF_SCALED;
    float* swarp = reinterpret_cast<float*>(smem + OFF_SWARP);
    float* sSp   = reinterpret_cast<float*>(smem + OFF_SS);
    float* sTp   = reinterpret_cast<float*>(smem + OFF_ST);
    char*  slots = smem + OFF_SLOTS;
    const uint32_t slots_u = sbase + OFF_SLOTS;

    const int tid = threadIdx.x;
    const int wid = tid >> 5;
    const int lid = tid & 31;

    if (tid == 0) {
        #pragma unroll
        for (int s = 0; s < NSLOTS; s++) {
            mbar_init(full0   + 8u * s, 1);     // TMA expect_tx completion
            mbar_init(scaled0 + 8u * s, NCW);   // one arrive per consumer warp
        }
    }
    __syncthreads();

    // chunks handled by this CTA
    const int nrows = (batch - blockIdx.x + gridDim.x - 1) / gridDim.x;
    const int T = nrows * CHUNKS_PER_ROW;

    if (wid == PROD_WARP) {
        // ---- fused producer: pipelined store + lagged load ----
        if (lid == 0) {
            float* dsts[NSLOTS];
            int s_slot = 0, sphase = 1;        // flipped: first NSLOTS waits pass

            const int GMAX = T + NSLOTS;       // NSLOTS > LAG
            for (int g = 0; g < GMAX; g++) {
                // ---- store stage: flush occupant of slot g%NSLOTS ----
                mbar_wait(scaled0 + 8u * s_slot, (uint32_t)sphase);
                if (g >= NSLOTS) {
                    fence_async_shared();
                    bulk_s2g(dsts[s_slot],
                             slots_u + (uint32_t)s_slot * CHUNK_BYTES,
                             CHUNK_BYTES);
                    bulk_commit();
                }
                if (++s_slot == NSLOTS) { s_slot = 0; sphase ^= 1; }

                // ---- load stage (lags by LAG iterations) ----
                const int cl = g - LAG;
                if (cl >= 0 && cl < T) {
                    const int l_slot = cl % NSLOTS;
                    bulk_wait_read<LAG>();     // that slot's store read drained
                    const int rl  = cl / CHUNKS_PER_ROW;
                    const int cc  = cl - rl * CHUNKS_PER_ROW;
                    const int r   = blockIdx.x + rl * gridDim.x;
                    const char* src = reinterpret_cast<const char*>(in)
                                    + (size_t)r * ROW_BYTES
                                    + (size_t)cc * CHUNK_BYTES;
                    dsts[l_slot] = out + (size_t)r * NUM_CLASSES
                                       + (size_t)cc * CHUNK_FLOATS;
                    mbar_expect_tx(full0 + 8u * l_slot, CHUNK_BYTES);
                    bulk_g2s(slots_u + (uint32_t)l_slot * CHUNK_BYTES,
                             src, CHUNK_BYTES,
                             full0 + 8u * l_slot);
                }
            }
            bulk_wait_all();   // all output stores complete before exit
        }
    } else {
        // ------- consumers (10 warps / 320 threads): sum, reduce, scale -------
        int slot = 0, cphase = 0;
        for (int r = blockIdx.x; r < batch; r += gridDim.x) {
            const int label = __ldg(labels + r);
            const int lvec  = label >> 2;
            const int lcomp = label & 3;
            const int c_l   = lvec / CHUNK_F4;    // chunk holding label elem
            const int loff  = lvec % CHUNK_F4;    // f4 index inside chunk

            const int row_slot0 = slot;

            // -- sum phase: exact partition, no bounds checks --
            float local = 0.0f;
            for (int c = 0; c < CHUNKS_PER_ROW; c++) {
                mbar_wait(full0 + 8u * slot, (uint32_t)cphase);
                const float4* ch =
                    reinterpret_cast<const float4*>(slots + (size_t)slot * CHUNK_BYTES);
                #pragma unroll
                for (int k = 0; k < F4_PER_THREAD; k++) {
                    float4 v = ch[tid + k * NCONS];
                    local += (v.x + v.y) + (v.z + v.w);
                }
                // grab label element while this chunk is guaranteed resident
                if (c == c_l && tid == 0) {
                    *sTp = *reinterpret_cast<const float*>(
                        slots + (size_t)slot * CHUNK_BYTES
                              + ((size_t)loff * 16 + (size_t)lcomp * 4));
                }
                if (++slot == NSLOTS) { slot = 0; cphase ^= 1; }
            }

            // -- reduce S across 10 warps --
            #pragma unroll
            for (int o = 16; o > 0; o >>= 1)
                local += __shfl_down_sync(0xffffffffu, local, o);
            if (lid == 0) swarp[wid] = local;
            asm volatile("bar.sync 1, %0;" :: "n"(NCONS) : "memory");
            if (wid == 0) {
                float v = (lid < NCW) ? swarp[lid] : 0.0f;
                #pragma unroll
                for (int o = 8; o > 0; o >>= 1)
                    v += __shfl_down_sync(0xffffffffu, v, o);
                if (lid == 0) *sSp = v;
            }
            asm volatile("bar.sync 1, %0;" :: "n"(NCONS) : "memory");

            const float S    = *sSp;
            const float t    = *sTp;
            const float s    = ALPHA / (1.0f + S - 2.0f * t);
            const float corr = 1.0f - s * S;

            // -- scale phase: in-place smem, hand slots to producer --
            int sslot = row_slot0;
            for (int c = 0; c < CHUNKS_PER_ROW; c++) {
                float4* ch =
                    reinterpret_cast<float4*>(slots + (size_t)sslot * CHUNK_BYTES);
                const bool lchunk = (c == c_l);
                #pragma unroll
                for (int k = 0; k < F4_PER_THREAD; k++) {
                    const int i = tid + k * NCONS;
                    float4 v = ch[i];
                    float4 o = make_float4(s * v.x, s * v.y, s * v.z, s * v.w);
                    if (lchunk && i == loff) {
                        o.x += (lcomp == 0) ? corr : 0.0f;
                        o.y += (lcomp == 1) ? corr : 0.0f;
                        o.z += (lcomp == 2) ? corr : 0.0f;
                        o.w += (lcomp == 3) ? corr : 0.0f;
                    }
                    ch[i] = o;
                }
                __syncwarp();
                if (lid == 0) mbar_arrive(scaled0 + 8u * sslot);
                if (++sslot == NSLOTS) sslot = 0;
            }
        }
    }
}

extern "C" void kernel_launch(void* const* d_in, const int* in_sizes, int n_in,
                              void* d_out, int out_size)
{
    const float* logits = (const float*)d_in[0];
    const int*   labels = (const int*)d_in[1];
    float*       out    = (float*)d_out;

    const int batch = in_sizes[1];

    cudaFuncSetAttribute(smooth_kernel,
                         cudaFuncAttributeMaxDynamicSharedMemorySize, SMEM_TOTAL);

    int dev = 0, sms = 148;
    cudaGetDevice(&dev);
    cudaDeviceGetAttribute(&sms, cudaDevAttrMultiProcessorCount, dev);
    int grid = sms < batch ? sms : batch;

    smooth_kernel<<<grid, THREADS, SMEM_TOTAL>>>(logits, labels, out, batch);
}